// round 15
// baseline (speedup 1.0000x reference)
#include <cuda_runtime.h>
#include <cuda_fp16.h>
#include <math.h>
#include <stdint.h>

#define BATCH 4
#define SEQ 2048
#define D_MODEL 512
#define NHEAD 8
#define HEAD_DIM 64
#define M_ROWS (BATCH * SEQ)      // 8192
#define QKV_N (3 * D_MODEL)       // 1536
#define K_DIM 512

// ------------------------ device scratch (all fp16) -------------------------
__device__ __half g_xh[M_ROWS * K_DIM];                     // x, fp16
__device__ __half g_q[BATCH * NHEAD * SEQ * HEAD_DIM];      // pre-scaled q
__device__ __half g_k[BATCH * NHEAD * SEQ * HEAD_DIM];
__device__ __half g_vt[BATCH * NHEAD * HEAD_DIM * SEQ];     // V^T [B,H,Hd,S]
__device__ __half g_att[M_ROWS * D_MODEL];                  // attn out [B,S,D]
__device__ __half g_wqkvt[QKV_N * K_DIM];                   // Wqkv^T fp16
__device__ __half g_wot[D_MODEL * D_MODEL];                 // Wo^T fp16

// ------------------------ helpers ------------------------------------------
__device__ __forceinline__ float ex2f(float x) {
    float y;
    asm("ex2.approx.f32 %0, %1;" : "=f"(y) : "f"(x));
    return y;
}

__device__ __forceinline__ uint32_t packh2(float lo, float hi) {
    uint32_t r;
    asm("cvt.rn.f16x2.f32 %0, %1, %2;" : "=r"(r) : "f"(hi), "f"(lo));
    return r;
}

__device__ __forceinline__ void mma_f16(float c[4], const uint32_t a[4],
                                        uint32_t b0, uint32_t b1) {
    asm volatile(
        "mma.sync.aligned.m16n8k16.row.col.f32.f16.f16.f32 "
        "{%0,%1,%2,%3}, {%4,%5,%6,%7}, {%8,%9}, {%0,%1,%2,%3};\n"
        : "+f"(c[0]), "+f"(c[1]), "+f"(c[2]), "+f"(c[3])
        : "r"(a[0]), "r"(a[1]), "r"(a[2]), "r"(a[3]), "r"(b0), "r"(b1));
}

__device__ __forceinline__ unsigned smem_u32(const void* p) {
    return (unsigned)__cvta_generic_to_shared(p);
}

#define LDSM_X4(d0, d1, d2, d3, addr) \
    asm volatile("ldmatrix.sync.aligned.m8n8.x4.shared.b16 {%0,%1,%2,%3}, [%4];" \
                 : "=r"(d0), "=r"(d1), "=r"(d2), "=r"(d3) : "r"(addr))

#define CP_ASYNC16(dst_u32, src_ptr) \
    asm volatile("cp.async.cg.shared.global [%0], [%1], 16;\n" \
                 :: "r"(dst_u32), "l"(src_ptr) : "memory")
#define CP_COMMIT()  asm volatile("cp.async.commit_group;" ::: "memory")
#define CP_WAIT(n)   asm volatile("cp.async.wait_group %0;" :: "n"(n) : "memory")

// ------------------------ x -> fp16 -----------------------------------------
__global__ __launch_bounds__(256)
void cvt_half_kernel(const float* __restrict__ in, __half* __restrict__ out)
{
    int idx = blockIdx.x * 256 + threadIdx.x;
    float4 v = ((const float4*)in)[idx];
    __half2 h0 = __floats2half2_rn(v.x, v.y);
    __half2 h1 = __floats2half2_rn(v.z, v.w);
    ((__half2*)out)[idx * 2] = h0;
    ((__half2*)out)[idx * 2 + 1] = h1;
}

// ------------------------ transpose+cvt: fp32 in[R][C] -> fp16 out[C][R] ----
__global__ __launch_bounds__(256)
void transpose_cvt_kernel(const float* __restrict__ in, __half* __restrict__ out,
                          int R, int C)
{
    __shared__ float tile[32][33];
    int cBase = blockIdx.x * 32, rBase = blockIdx.y * 32;
    int tx = threadIdx.x, ty = threadIdx.y;
#pragma unroll
    for (int i = 0; i < 32; i += 8)
        tile[ty + i][tx] = in[(size_t)(rBase + ty + i) * C + cBase + tx];
    __syncthreads();
#pragma unroll
    for (int i = 0; i < 32; i += 8)
        out[(size_t)(cBase + ty + i) * R + rBase + tx] = __float2half(tile[tx][ty + i]);
}

// ------------------------ fp16 GEMM (3-stage pipeline + LDSM, R14 proven) ----
#define GS 40                       // halves per row (32 data + 8 pad)
#define G_STAGE_H (2 * 128 * GS)    // halves per stage (As + Bs) = 10240
#define GEMM_SMEM (3 * G_STAGE_H * 2)   // 61440 bytes
#define G_NT (K_DIM / 32)           // 16 k-iterations

template <int MODE>
__global__ __launch_bounds__(256, 2)
void gemm_f16(const __half* __restrict__ A, const __half* __restrict__ Bt,
              const float* __restrict__ bias, float* __restrict__ C, int N)
{
    extern __shared__ __half smg[];

    const int tid = threadIdx.x;
    const int lane = tid & 31;
    const int warp = tid >> 5;
    const int wm = warp >> 2;
    const int wn = warp & 3;
    const int lr = lane >> 2;
    const int lc = lane & 3;
    const int rowin = lane & 7;          // ldmatrix row within 8x8 tile
    const int selB = (lane >> 3) & 1;    // matrix selector bit 0
    const int selH = lane >> 4;          // matrix selector bit 1
    const int mBase = blockIdx.y * 128;
    const int nBase = blockIdx.x * 128;

    const int cpRow = tid >> 2;
    const int cpSeg = (tid & 3) * 8;

    auto issue_stage = [&](int st, int k0) {
        __half* As = smg + st * G_STAGE_H;
        __half* Bs = As + 128 * GS;
#pragma unroll
        for (int i = 0; i < 2; i++) {
            int row = cpRow + i * 64;
            CP_ASYNC16(smem_u32(&As[row * GS + cpSeg]),
                       &A[(size_t)(mBase + row) * K_DIM + k0 + cpSeg]);
            CP_ASYNC16(smem_u32(&Bs[row * GS + cpSeg]),
                       &Bt[(size_t)(nBase + row) * K_DIM + k0 + cpSeg]);
        }
        CP_COMMIT();
    };

    float acc[4][4][4];
#pragma unroll
    for (int mt = 0; mt < 4; mt++)
#pragma unroll
        for (int nt = 0; nt < 4; nt++)
#pragma unroll
            for (int j = 0; j < 4; j++) acc[mt][nt][j] = 0.f;

    issue_stage(0, 0);
    issue_stage(1, 32);

    for (int t = 0; t < G_NT; t++) {
        if (t < G_NT - 1) { CP_WAIT(1); } else { CP_WAIT(0); }
        __syncthreads();
        if (t + 2 < G_NT) issue_stage((t + 2) % 3, (t + 2) * 32);

        const __half* As = smg + (t % 3) * G_STAGE_H;
        const __half* Bs = As + 128 * GS;

#pragma unroll
        for (int kk = 0; kk < 2; kk++) {
            uint32_t af[4][4];
#pragma unroll
            for (int mt = 0; mt < 4; mt++) {
                int row = wm * 64 + mt * 16 + selB * 8 + rowin;
                int col = kk * 16 + selH * 8;
                LDSM_X4(af[mt][0], af[mt][1], af[mt][2], af[mt][3],
                        smem_u32(&As[row * GS + col]));
            }
            uint32_t bf[4][2];
#pragma unroll
            for (int p = 0; p < 2; p++) {
                int row = wn * 32 + (p * 2 + selH) * 8 + rowin;
                int col = kk * 16 + selB * 8;
                LDSM_X4(bf[2 * p][0], bf[2 * p][1], bf[2 * p + 1][0], bf[2 * p + 1][1],
                        smem_u32(&Bs[row * GS + col]));
            }
#pragma unroll
            for (int nt = 0; nt < 4; nt++)
#pragma unroll
                for (int mt = 0; mt < 4; mt++)
                    mma_f16(acc[mt][nt], af[mt], bf[nt][0], bf[nt][1]);
        }
    }

    const float QS = 0.18033688011112042f;   // 1/8 * log2(e)
#pragma unroll
    for (int mt = 0; mt < 4; mt++) {
#pragma unroll
        for (int nt = 0; nt < 4; nt++) {
            int grow0 = mBase + wm * 64 + mt * 16 + lr;
            int gcol = nBase + wn * 32 + nt * 8 + 2 * lc;
            float b0v = bias[gcol], b1v = bias[gcol + 1];
            if (MODE == 0) {
                *(float2*)&C[(size_t)grow0 * N + gcol] =
                    make_float2(acc[mt][nt][0] + b0v, acc[mt][nt][1] + b1v);
                *(float2*)&C[(size_t)(grow0 + 8) * N + gcol] =
                    make_float2(acc[mt][nt][2] + b0v, acc[mt][nt][3] + b1v);
            } else {
                int region = gcol >> 9;          // 0=q, 1=k, 2=v
                int h = (gcol >> 6) & 7;
                int d = gcol & 63;               // even
#pragma unroll
                for (int rr = 0; rr < 2; rr++) {
                    int grow = grow0 + rr * 8;
                    int bb = grow >> 11;
                    int ss = grow & (SEQ - 1);
                    float x1 = acc[mt][nt][2 * rr] + b0v;
                    float x2 = acc[mt][nt][2 * rr + 1] + b1v;
                    if (region == 2) {
                        size_t base = ((size_t)(bb * NHEAD + h) * HEAD_DIM + d) * SEQ + ss;
                        g_vt[base] = __float2half(x1);
                        g_vt[base + SEQ] = __float2half(x2);
                    } else {
                        float inv_freq = __powf(10000.f, -(float)d * (1.f / 64.f));
                        float sn, cs;
                        __sincosf((float)ss * inv_freq, &sn, &cs);
                        float r1 = x1 * cs - x2 * sn;
                        float r2 = x1 * sn + x2 * cs;
                        size_t off = (size_t)((bb * NHEAD + h) * SEQ + ss) * HEAD_DIM + d;
                        if (region == 0)
                            *(__half2*)&g_q[off] = __floats2half2_rn(r1 * QS, r2 * QS);
                        else
                            *(__half2*)&g_k[off] = __floats2half2_rn(r1, r2);
                    }
                }
            }
        }
    }
}

// ------------------------ attention fp16 (R14 body, 3 CTAs/SM) ---------------
#define AT_S 72
#define AT_STAGE (2 * 64 * AT_S)            // K + V^T tiles, halves = 9216

__global__ __launch_bounds__(128, 3)
void attention_f16()
{
    __shared__ __half smh[2 * AT_STAGE];    // 36864 bytes

    const int tid = threadIdx.x;
    const int lane = tid & 31;
    const int w = tid >> 5;
    const int lr = lane >> 2;
    const int lc = lane & 3;
    const int rowin = lane & 7;
    const int selB = (lane >> 3) & 1;
    const int selH = lane >> 4;
    const int bh = blockIdx.y;
    const int bb = bh >> 3, hh = bh & 7;
    const int row0 = blockIdx.x * 128;

    const __half* qg = g_q + (size_t)bh * SEQ * HEAD_DIM;
    const __half* kg = g_k + (size_t)bh * SEQ * HEAD_DIM;
    const __half* vtg = g_vt + (size_t)bh * HEAD_DIM * SEQ;

    // ---- stage Q (already scaled+fp16), extract m16n8k16 A fragments
#pragma unroll
    for (int i = 0; i < 8; i++) {
        int idx = tid + 128 * i;
        int row = idx >> 3, seg = (idx & 7) * 8;
        *(uint4*)&smh[row * AT_S + seg] =
            *(const uint4*)&qg[(size_t)(row0 + row) * HEAD_DIM + seg];
    }
    __syncthreads();

    const int r0 = w * 32 + lr;
    uint32_t qa[4][8];                      // [kk16][mt0:a0..a3, mt1:a0..a3]
#pragma unroll
    for (int kk = 0; kk < 4; kk++) {
        int col = kk * 16 + 2 * lc;
        qa[kk][0] = *(const uint32_t*)&smh[(r0) * AT_S + col];
        qa[kk][1] = *(const uint32_t*)&smh[(r0 + 8) * AT_S + col];
        qa[kk][2] = *(const uint32_t*)&smh[(r0) * AT_S + col + 8];
        qa[kk][3] = *(const uint32_t*)&smh[(r0 + 8) * AT_S + col + 8];
        qa[kk][4] = *(const uint32_t*)&smh[(r0 + 16) * AT_S + col];
        qa[kk][5] = *(const uint32_t*)&smh[(r0 + 24) * AT_S + col];
        qa[kk][6] = *(const uint32_t*)&smh[(r0 + 16) * AT_S + col + 8];
        qa[kk][7] = *(const uint32_t*)&smh[(r0 + 24) * AT_S + col + 8];
    }
    __syncthreads();

    // ---- prefetch tile 0
    {
        __half* Ksb = smh;
        __half* Vsb = smh + 64 * AT_S;
#pragma unroll
        for (int i = 0; i < 4; i++) {
            int idx = tid + 128 * i;
            int row = idx >> 3, seg = (idx & 7) * 8;
            CP_ASYNC16(smem_u32(&Ksb[row * AT_S + seg]),
                       &kg[(size_t)row * HEAD_DIM + seg]);
            CP_ASYNC16(smem_u32(&Vsb[row * AT_S + seg]),
                       &vtg[(size_t)row * SEQ + seg]);
        }
        CP_COMMIT();
    }

    float o[2][8][4];
#pragma unroll
    for (int mt = 0; mt < 2; mt++)
#pragma unroll
        for (int nt = 0; nt < 8; nt++)
#pragma unroll
            for (int j = 0; j < 4; j++) o[mt][nt][j] = 0.f;
    float l[4] = {0.f, 0.f, 0.f, 0.f};

    for (int t = 0; t < SEQ / 64; t++) {
        if (t < SEQ / 64 - 1) {
            __half* Ksb = smh + ((t + 1) & 1) * AT_STAGE;
            __half* Vsb = Ksb + 64 * AT_S;
#pragma unroll
            for (int i = 0; i < 4; i++) {
                int idx = tid + 128 * i;
                int row = idx >> 3, seg = (idx & 7) * 8;
                CP_ASYNC16(smem_u32(&Ksb[row * AT_S + seg]),
                           &kg[(size_t)((t + 1) * 64 + row) * HEAD_DIM + seg]);
                CP_ASYNC16(smem_u32(&Vsb[row * AT_S + seg]),
                           &vtg[(size_t)row * SEQ + (t + 1) * 64 + seg]);
            }
            CP_COMMIT();
            CP_WAIT(1);
        } else {
            CP_WAIT(0);
        }
        __syncthreads();

        const __half* Ks = smh + (t & 1) * AT_STAGE;
        const __half* Vs = Ks + 64 * AT_S;

        // two 32-key sub-blocks per tile
#pragma unroll
        for (int half = 0; half < 2; half++) {
            // ---- scores: Sc[32 x 32] = Q @ K^T; B frags via LDSM.x4
            float sc[2][4][4];
#pragma unroll
            for (int mt = 0; mt < 2; mt++)
#pragma unroll
                for (int nt = 0; nt < 4; nt++)
#pragma unroll
                    for (int j = 0; j < 4; j++) sc[mt][nt][j] = 0.f;

#pragma unroll
            for (int nt = 0; nt < 4; nt++) {
                int krow = half * 32 + nt * 8 + rowin;
                uint32_t kb[4][2];   // [kk][b0/b1]
                {
                    int col = selH * 16 + selB * 8;            // kk 0,1
                    LDSM_X4(kb[0][0], kb[0][1], kb[1][0], kb[1][1],
                            smem_u32(&Ks[krow * AT_S + col]));
                }
                {
                    int col = 32 + selH * 16 + selB * 8;       // kk 2,3
                    LDSM_X4(kb[2][0], kb[2][1], kb[3][0], kb[3][1],
                            smem_u32(&Ks[krow * AT_S + col]));
                }
#pragma unroll
                for (int kk = 0; kk < 4; kk++) {
                    mma_f16(sc[0][nt], &qa[kk][0], kb[kk][0], kb[kk][1]);
                    mma_f16(sc[1][nt], &qa[kk][4], kb[kk][0], kb[kk][1]);
                }
            }

            // ---- p = 2^s (no max subtraction), accumulate partial l
#pragma unroll
            for (int mt = 0; mt < 2; mt++) {
#pragma unroll
                for (int nt = 0; nt < 4; nt++) {
                    float p0 = ex2f(sc[mt][nt][0]);
                    float p1 = ex2f(sc[mt][nt][1]);
                    float p2 = ex2f(sc[mt][nt][2]);
                    float p3 = ex2f(sc[mt][nt][3]);
                    l[2 * mt] += p0 + p1;
                    l[2 * mt + 1] += p2 + p3;
                    sc[mt][nt][0] = p0; sc[mt][nt][1] = p1;
                    sc[mt][nt][2] = p2; sc[mt][nt][3] = p3;
                }
            }

            // ---- O += P @ V; V frags via LDSM.x4
            uint32_t pa[2][2][4];    // [kkp][mt][4]
#pragma unroll
            for (int mt = 0; mt < 2; mt++)
#pragma unroll
                for (int kkp = 0; kkp < 2; kkp++) {
                    pa[kkp][mt][0] = packh2(sc[mt][2 * kkp][0], sc[mt][2 * kkp][1]);
                    pa[kkp][mt][1] = packh2(sc[mt][2 * kkp][2], sc[mt][2 * kkp][3]);
                    pa[kkp][mt][2] = packh2(sc[mt][2 * kkp + 1][0], sc[mt][2 * kkp + 1][1]);
                    pa[kkp][mt][3] = packh2(sc[mt][2 * kkp + 1][2], sc[mt][2 * kkp + 1][3]);
                }

            int colv = half * 32 + selH * 16 + selB * 8;
#pragma unroll
            for (int nt = 0; nt < 8; nt++) {
                int drow = nt * 8 + rowin;
                uint32_t v00, v01, v10, v11;
                LDSM_X4(v00, v01, v10, v11, smem_u32(&Vs[drow * AT_S + colv]));
                mma_f16(o[0][nt], pa[0][0], v00, v01);
                mma_f16(o[1][nt], pa[0][1], v00, v01);
                mma_f16(o[0][nt], pa[1][0], v10, v11);
                mma_f16(o[1][nt], pa[1][1], v10, v11);
            }
        }
        __syncthreads();
    }

    // ---- epilogue: reduce l across the quad once, normalize, write [B,S,D]
#pragma unroll
    for (int j = 0; j < 4; j++) {
        l[j] += __shfl_xor_sync(0xffffffffu, l[j], 1);
        l[j] += __shfl_xor_sync(0xffffffffu, l[j], 2);
    }
#pragma unroll
    for (int mt = 0; mt < 2; mt++) {
        float il0 = 1.f / l[2 * mt], il1 = 1.f / l[2 * mt + 1];
        int srow = row0 + w * 32 + mt * 16 + lr;
#pragma unroll
        for (int nt = 0; nt < 8; nt++) {
            int d = hh * 64 + nt * 8 + 2 * lc;
            *(__half2*)&g_att[(size_t)(bb * SEQ + srow) * D_MODEL + d] =
                __floats2half2_rn(o[mt][nt][0] * il0, o[mt][nt][1] * il0);
            *(__half2*)&g_att[(size_t)(bb * SEQ + srow + 8) * D_MODEL + d] =
                __floats2half2_rn(o[mt][nt][2] * il1, o[mt][nt][3] * il1);
        }
    }
}

// ------------------------ launch --------------------------------------------
extern "C" void kernel_launch(void* const* d_in, const int* in_sizes, int n_in,
                              void* d_out, int out_size)
{
    const float* x    = (const float*)d_in[0];
    const float* Wqkv = (const float*)d_in[1];
    const float* bqkv = (const float*)d_in[2];
    const float* Wo   = (const float*)d_in[3];
    const float* bo   = (const float*)d_in[4];
    float* out = (float*)d_out;

    __half *p_xh, *p_att, *p_wqkvt, *p_wot;
    cudaGetSymbolAddress((void**)&p_xh, g_xh);
    cudaGetSymbolAddress((void**)&p_att, g_att);
    cudaGetSymbolAddress((void**)&p_wqkvt, g_wqkvt);
    cudaGetSymbolAddress((void**)&p_wot, g_wot);

    // x -> fp16; weights transposed + fp16
    cvt_half_kernel<<<M_ROWS * K_DIM / 4 / 256, 256>>>(x, p_xh);
    {
        dim3 blk(32, 8);
        transpose_cvt_kernel<<<dim3(QKV_N / 32, K_DIM / 32), blk>>>(Wqkv, p_wqkvt, K_DIM, QKV_N);
        transpose_cvt_kernel<<<dim3(D_MODEL / 32, K_DIM / 32), blk>>>(Wo, p_wot, K_DIM, D_MODEL);
    }
    // QKV projection + RoPE + split (fp16 q/k/vt, q pre-scaled)
    {
        cudaFuncSetAttribute(gemm_f16<1>,
                             cudaFuncAttributeMaxDynamicSharedMemorySize, GEMM_SMEM);
        dim3 grid(QKV_N / 128, M_ROWS / 128);
        gemm_f16<1><<<grid, 256, GEMM_SMEM>>>(p_xh, p_wqkvt, bqkv, nullptr, QKV_N);
    }
    // attention
    {
        dim3 grid(SEQ / 128, BATCH * NHEAD);
        attention_f16<<<grid, 128>>>();
    }
    // output projection (fp32 out)
    {
        cudaFuncSetAttribute(gemm_f16<0>,
                             cudaFuncAttributeMaxDynamicSharedMemorySize, GEMM_SMEM);
        dim3 grid(D_MODEL / 128, M_ROWS / 128);
        gemm_f16<0><<<grid, 256, GEMM_SMEM>>>(p_att, p_wot, bo, out, D_MODEL);
    }
}

// round 16
// speedup vs baseline: 1.0921x; 1.0921x over previous
#include <cuda_runtime.h>
#include <cuda_fp16.h>
#include <math.h>
#include <stdint.h>

#define BATCH 4
#define SEQ 2048
#define D_MODEL 512
#define NHEAD 8
#define HEAD_DIM 64
#define M_ROWS (BATCH * SEQ)      // 8192
#define QKV_N (3 * D_MODEL)       // 1536
#define K_DIM 512

// ------------------------ device scratch (all fp16) -------------------------
__device__ __half g_xh[M_ROWS * K_DIM];                     // x, fp16
__device__ __half g_q[BATCH * NHEAD * SEQ * HEAD_DIM];      // pre-scaled q
__device__ __half g_k[BATCH * NHEAD * SEQ * HEAD_DIM];
__device__ __half g_vt[BATCH * NHEAD * HEAD_DIM * SEQ];     // V^T [B,H,Hd,S]
__device__ __half g_att[M_ROWS * D_MODEL];                  // attn out [B,S,D]
__device__ __half g_wqkvt[QKV_N * K_DIM];                   // Wqkv^T fp16
__device__ __half g_wot[D_MODEL * D_MODEL];                 // Wo^T fp16

// ------------------------ helpers ------------------------------------------
__device__ __forceinline__ float ex2f(float x) {
    float y;
    asm("ex2.approx.f32 %0, %1;" : "=f"(y) : "f"(x));
    return y;
}

__device__ __forceinline__ uint32_t packh2(float lo, float hi) {
    uint32_t r;
    asm("cvt.rn.f16x2.f32 %0, %1, %2;" : "=r"(r) : "f"(hi), "f"(lo));
    return r;
}

__device__ __forceinline__ void mma_f16(float c[4], const uint32_t a[4],
                                        uint32_t b0, uint32_t b1) {
    asm volatile(
        "mma.sync.aligned.m16n8k16.row.col.f32.f16.f16.f32 "
        "{%0,%1,%2,%3}, {%4,%5,%6,%7}, {%8,%9}, {%0,%1,%2,%3};\n"
        : "+f"(c[0]), "+f"(c[1]), "+f"(c[2]), "+f"(c[3])
        : "r"(a[0]), "r"(a[1]), "r"(a[2]), "r"(a[3]), "r"(b0), "r"(b1));
}

__device__ __forceinline__ unsigned smem_u32(const void* p) {
    return (unsigned)__cvta_generic_to_shared(p);
}

#define LDSM_X4(d0, d1, d2, d3, addr) \
    asm volatile("ldmatrix.sync.aligned.m8n8.x4.shared.b16 {%0,%1,%2,%3}, [%4];" \
                 : "=r"(d0), "=r"(d1), "=r"(d2), "=r"(d3) : "r"(addr))

#define CP_ASYNC16(dst_u32, src_ptr) \
    asm volatile("cp.async.cg.shared.global [%0], [%1], 16;\n" \
                 :: "r"(dst_u32), "l"(src_ptr) : "memory")
#define CP_COMMIT()  asm volatile("cp.async.commit_group;" ::: "memory")
#define CP_WAIT(n)   asm volatile("cp.async.wait_group %0;" :: "n"(n) : "memory")

// ------------------------ fused prepass --------------------------------------
// blocks [0, 4096): x -> fp16 (float4 per thread)
// blocks [4096, 4864): Wqkv transpose+cvt (48 x 16 tiles)
// blocks [4864, 5120): Wo transpose+cvt (16 x 16 tiles)
__global__ __launch_bounds__(256)
void prepass_kernel(const float* __restrict__ x,
                    const float* __restrict__ Wqkv,
                    const float* __restrict__ Wo)
{
    int bid = blockIdx.x;
    int tid = threadIdx.x;

    if (bid < 4096) {
        int idx = bid * 256 + tid;
        float4 v = ((const float4*)x)[idx];
        ((__half2*)g_xh)[idx * 2]     = __floats2half2_rn(v.x, v.y);
        ((__half2*)g_xh)[idx * 2 + 1] = __floats2half2_rn(v.z, v.w);
        return;
    }

    __shared__ float tile[32][33];
    const float* in;
    __half* out;
    int R = K_DIM, C, bx, by;
    if (bid < 4096 + 768) {
        int b2 = bid - 4096;
        in = Wqkv; out = g_wqkvt; C = QKV_N;
        bx = b2 % 48; by = b2 / 48;
    } else {
        int b3 = bid - 4096 - 768;
        in = Wo; out = g_wot; C = D_MODEL;
        bx = b3 % 16; by = b3 / 16;
    }
    int tx = tid & 31, ty = tid >> 5;
    int cBase = bx * 32, rBase = by * 32;
#pragma unroll
    for (int i = 0; i < 32; i += 8)
        tile[ty + i][tx] = in[(size_t)(rBase + ty + i) * C + cBase + tx];
    __syncthreads();
#pragma unroll
    for (int i = 0; i < 32; i += 8)
        out[(size_t)(cBase + ty + i) * R + rBase + tx] = __float2half(tile[tx][ty + i]);
}

// ------------------------ fp16 GEMM (3-stage pipeline + LDSM, R14 proven) ----
#define GS 40                       // halves per row (32 data + 8 pad)
#define G_STAGE_H (2 * 128 * GS)    // halves per stage (As + Bs) = 10240
#define GEMM_SMEM (3 * G_STAGE_H * 2)   // 61440 bytes
#define G_NT (K_DIM / 32)           // 16 k-iterations

template <int MODE>
__global__ __launch_bounds__(256, 2)
void gemm_f16(const __half* __restrict__ A, const __half* __restrict__ Bt,
              const float* __restrict__ bias, float* __restrict__ C, int N)
{
    extern __shared__ __half smg[];

    const int tid = threadIdx.x;
    const int lane = tid & 31;
    const int warp = tid >> 5;
    const int wm = warp >> 2;
    const int wn = warp & 3;
    const int lr = lane >> 2;
    const int lc = lane & 3;
    const int rowin = lane & 7;
    const int selB = (lane >> 3) & 1;
    const int selH = lane >> 4;
    const int mBase = blockIdx.y * 128;
    const int nBase = blockIdx.x * 128;

    const int cpRow = tid >> 2;
    const int cpSeg = (tid & 3) * 8;

    auto issue_stage = [&](int st, int k0) {
        __half* As = smg + st * G_STAGE_H;
        __half* Bs = As + 128 * GS;
#pragma unroll
        for (int i = 0; i < 2; i++) {
            int row = cpRow + i * 64;
            CP_ASYNC16(smem_u32(&As[row * GS + cpSeg]),
                       &A[(size_t)(mBase + row) * K_DIM + k0 + cpSeg]);
            CP_ASYNC16(smem_u32(&Bs[row * GS + cpSeg]),
                       &Bt[(size_t)(nBase + row) * K_DIM + k0 + cpSeg]);
        }
        CP_COMMIT();
    };

    float acc[4][4][4];
#pragma unroll
    for (int mt = 0; mt < 4; mt++)
#pragma unroll
        for (int nt = 0; nt < 4; nt++)
#pragma unroll
            for (int j = 0; j < 4; j++) acc[mt][nt][j] = 0.f;

    issue_stage(0, 0);
    issue_stage(1, 32);

    for (int t = 0; t < G_NT; t++) {
        if (t < G_NT - 1) { CP_WAIT(1); } else { CP_WAIT(0); }
        __syncthreads();
        if (t + 2 < G_NT) issue_stage((t + 2) % 3, (t + 2) * 32);

        const __half* As = smg + (t % 3) * G_STAGE_H;
        const __half* Bs = As + 128 * GS;

#pragma unroll
        for (int kk = 0; kk < 2; kk++) {
            uint32_t af[4][4];
#pragma unroll
            for (int mt = 0; mt < 4; mt++) {
                int row = wm * 64 + mt * 16 + selB * 8 + rowin;
                int col = kk * 16 + selH * 8;
                LDSM_X4(af[mt][0], af[mt][1], af[mt][2], af[mt][3],
                        smem_u32(&As[row * GS + col]));
            }
            uint32_t bf[4][2];
#pragma unroll
            for (int p = 0; p < 2; p++) {
                int row = wn * 32 + (p * 2 + selH) * 8 + rowin;
                int col = kk * 16 + selB * 8;
                LDSM_X4(bf[2 * p][0], bf[2 * p][1], bf[2 * p + 1][0], bf[2 * p + 1][1],
                        smem_u32(&Bs[row * GS + col]));
            }
#pragma unroll
            for (int nt = 0; nt < 4; nt++)
#pragma unroll
                for (int mt = 0; mt < 4; mt++)
                    mma_f16(acc[mt][nt], af[mt], bf[nt][0], bf[nt][1]);
        }
    }

    const float QS = 0.18033688011112042f;   // 1/8 * log2(e)
#pragma unroll
    for (int mt = 0; mt < 4; mt++) {
#pragma unroll
        for (int nt = 0; nt < 4; nt++) {
            int grow0 = mBase + wm * 64 + mt * 16 + lr;
            int gcol = nBase + wn * 32 + nt * 8 + 2 * lc;
            float b0v = bias[gcol], b1v = bias[gcol + 1];
            if (MODE == 0) {
                *(float2*)&C[(size_t)grow0 * N + gcol] =
                    make_float2(acc[mt][nt][0] + b0v, acc[mt][nt][1] + b1v);
                *(float2*)&C[(size_t)(grow0 + 8) * N + gcol] =
                    make_float2(acc[mt][nt][2] + b0v, acc[mt][nt][3] + b1v);
            } else {
                int region = gcol >> 9;          // 0=q, 1=k, 2=v
                int h = (gcol >> 6) & 7;
                int d = gcol & 63;               // even
#pragma unroll
                for (int rr = 0; rr < 2; rr++) {
                    int grow = grow0 + rr * 8;
                    int bb = grow >> 11;
                    int ss = grow & (SEQ - 1);
                    float x1 = acc[mt][nt][2 * rr] + b0v;
                    float x2 = acc[mt][nt][2 * rr + 1] + b1v;
                    if (region == 2) {
                        size_t base = ((size_t)(bb * NHEAD + h) * HEAD_DIM + d) * SEQ + ss;
                        g_vt[base] = __float2half(x1);
                        g_vt[base + SEQ] = __float2half(x2);
                    } else {
                        float inv_freq = __powf(10000.f, -(float)d * (1.f / 64.f));
                        float sn, cs;
                        __sincosf((float)ss * inv_freq, &sn, &cs);
                        float r1 = x1 * cs - x2 * sn;
                        float r2 = x1 * sn + x2 * cs;
                        size_t off = (size_t)((bb * NHEAD + h) * SEQ + ss) * HEAD_DIM + d;
                        if (region == 0)
                            *(__half2*)&g_q[off] = __floats2half2_rn(r1 * QS, r2 * QS);
                        else
                            *(__half2*)&g_k[off] = __floats2half2_rn(r1, r2);
                    }
                }
            }
        }
    }
}

// ------------------------ attention fp16 (R14 body, 3-stage ring) ------------
#define AT_S 72
#define AT_STAGE (2 * 64 * AT_S)            // K + V^T tiles, halves = 9216
#define AT_SMEM (3 * AT_STAGE * 2)          // 55296 bytes (dynamic)
#define AT_NT (SEQ / 64)                    // 32 key tiles

__global__ __launch_bounds__(128, 2)
void attention_f16()
{
    extern __shared__ __half smh[];

    const int tid = threadIdx.x;
    const int lane = tid & 31;
    const int w = tid >> 5;
    const int lr = lane >> 2;
    const int lc = lane & 3;
    const int rowin = lane & 7;
    const int selB = (lane >> 3) & 1;
    const int selH = lane >> 4;
    const int bh = blockIdx.y;
    const int bb = bh >> 3, hh = bh & 7;
    const int row0 = blockIdx.x * 128;

    const __half* qg = g_q + (size_t)bh * SEQ * HEAD_DIM;
    const __half* kg = g_k + (size_t)bh * SEQ * HEAD_DIM;
    const __half* vtg = g_vt + (size_t)bh * HEAD_DIM * SEQ;

    // ---- stage Q (already scaled+fp16), extract m16n8k16 A fragments
#pragma unroll
    for (int i = 0; i < 8; i++) {
        int idx = tid + 128 * i;
        int row = idx >> 3, seg = (idx & 7) * 8;
        *(uint4*)&smh[row * AT_S + seg] =
            *(const uint4*)&qg[(size_t)(row0 + row) * HEAD_DIM + seg];
    }
    __syncthreads();

    const int r0 = w * 32 + lr;
    uint32_t qa[4][8];
#pragma unroll
    for (int kk = 0; kk < 4; kk++) {
        int col = kk * 16 + 2 * lc;
        qa[kk][0] = *(const uint32_t*)&smh[(r0) * AT_S + col];
        qa[kk][1] = *(const uint32_t*)&smh[(r0 + 8) * AT_S + col];
        qa[kk][2] = *(const uint32_t*)&smh[(r0) * AT_S + col + 8];
        qa[kk][3] = *(const uint32_t*)&smh[(r0 + 8) * AT_S + col + 8];
        qa[kk][4] = *(const uint32_t*)&smh[(r0 + 16) * AT_S + col];
        qa[kk][5] = *(const uint32_t*)&smh[(r0 + 24) * AT_S + col];
        qa[kk][6] = *(const uint32_t*)&smh[(r0 + 16) * AT_S + col + 8];
        qa[kk][7] = *(const uint32_t*)&smh[(r0 + 24) * AT_S + col + 8];
    }
    __syncthreads();

    // stage issuance helper
    auto issue_tile = [&](int st, int t) {
        __half* Ksb = smh + st * AT_STAGE;
        __half* Vsb = Ksb + 64 * AT_S;
#pragma unroll
        for (int i = 0; i < 4; i++) {
            int idx = tid + 128 * i;
            int row = idx >> 3, seg = (idx & 7) * 8;
            CP_ASYNC16(smem_u32(&Ksb[row * AT_S + seg]),
                       &kg[(size_t)(t * 64 + row) * HEAD_DIM + seg]);
            CP_ASYNC16(smem_u32(&Vsb[row * AT_S + seg]),
                       &vtg[(size_t)row * SEQ + t * 64 + seg]);
        }
        CP_COMMIT();
    };

    issue_tile(0, 0);
    issue_tile(1, 1);

    float o[2][8][4];
#pragma unroll
    for (int mt = 0; mt < 2; mt++)
#pragma unroll
        for (int nt = 0; nt < 8; nt++)
#pragma unroll
            for (int j = 0; j < 4; j++) o[mt][nt][j] = 0.f;
    float l[4] = {0.f, 0.f, 0.f, 0.f};

    for (int t = 0; t < AT_NT; t++) {
        if (t < AT_NT - 1) { CP_WAIT(1); } else { CP_WAIT(0); }
        __syncthreads();
        if (t + 2 < AT_NT) issue_tile((t + 2) % 3, t + 2);

        const __half* Ks = smh + (t % 3) * AT_STAGE;
        const __half* Vs = Ks + 64 * AT_S;

        // two 32-key sub-blocks per tile
#pragma unroll
        for (int half = 0; half < 2; half++) {
            float sc[2][4][4];
#pragma unroll
            for (int mt = 0; mt < 2; mt++)
#pragma unroll
                for (int nt = 0; nt < 4; nt++)
#pragma unroll
                    for (int j = 0; j < 4; j++) sc[mt][nt][j] = 0.f;

#pragma unroll
            for (int nt = 0; nt < 4; nt++) {
                int krow = half * 32 + nt * 8 + rowin;
                uint32_t kb[4][2];
                {
                    int col = selH * 16 + selB * 8;
                    LDSM_X4(kb[0][0], kb[0][1], kb[1][0], kb[1][1],
                            smem_u32(&Ks[krow * AT_S + col]));
                }
                {
                    int col = 32 + selH * 16 + selB * 8;
                    LDSM_X4(kb[2][0], kb[2][1], kb[3][0], kb[3][1],
                            smem_u32(&Ks[krow * AT_S + col]));
                }
#pragma unroll
                for (int kk = 0; kk < 4; kk++) {
                    mma_f16(sc[0][nt], &qa[kk][0], kb[kk][0], kb[kk][1]);
                    mma_f16(sc[1][nt], &qa[kk][4], kb[kk][0], kb[kk][1]);
                }
            }

            // p = 2^s, accumulate partial l
#pragma unroll
            for (int mt = 0; mt < 2; mt++) {
#pragma unroll
                for (int nt = 0; nt < 4; nt++) {
                    float p0 = ex2f(sc[mt][nt][0]);
                    float p1 = ex2f(sc[mt][nt][1]);
                    float p2 = ex2f(sc[mt][nt][2]);
                    float p3 = ex2f(sc[mt][nt][3]);
                    l[2 * mt] += p0 + p1;
                    l[2 * mt + 1] += p2 + p3;
                    sc[mt][nt][0] = p0; sc[mt][nt][1] = p1;
                    sc[mt][nt][2] = p2; sc[mt][nt][3] = p3;
                }
            }

            // O += P @ V
            uint32_t pa[2][2][4];
#pragma unroll
            for (int mt = 0; mt < 2; mt++)
#pragma unroll
                for (int kkp = 0; kkp < 2; kkp++) {
                    pa[kkp][mt][0] = packh2(sc[mt][2 * kkp][0], sc[mt][2 * kkp][1]);
                    pa[kkp][mt][1] = packh2(sc[mt][2 * kkp][2], sc[mt][2 * kkp][3]);
                    pa[kkp][mt][2] = packh2(sc[mt][2 * kkp + 1][0], sc[mt][2 * kkp + 1][1]);
                    pa[kkp][mt][3] = packh2(sc[mt][2 * kkp + 1][2], sc[mt][2 * kkp + 1][3]);
                }

            int colv = half * 32 + selH * 16 + selB * 8;
#pragma unroll
            for (int nt = 0; nt < 8; nt++) {
                int drow = nt * 8 + rowin;
                uint32_t v00, v01, v10, v11;
                LDSM_X4(v00, v01, v10, v11, smem_u32(&Vs[drow * AT_S + colv]));
                mma_f16(o[0][nt], pa[0][0], v00, v01);
                mma_f16(o[1][nt], pa[0][1], v00, v01);
                mma_f16(o[0][nt], pa[1][0], v10, v11);
                mma_f16(o[1][nt], pa[1][1], v10, v11);
            }
        }
    }

    // ---- epilogue
#pragma unroll
    for (int j = 0; j < 4; j++) {
        l[j] += __shfl_xor_sync(0xffffffffu, l[j], 1);
        l[j] += __shfl_xor_sync(0xffffffffu, l[j], 2);
    }
#pragma unroll
    for (int mt = 0; mt < 2; mt++) {
        float il0 = 1.f / l[2 * mt], il1 = 1.f / l[2 * mt + 1];
        int srow = row0 + w * 32 + mt * 16 + lr;
#pragma unroll
        for (int nt = 0; nt < 8; nt++) {
            int d = hh * 64 + nt * 8 + 2 * lc;
            *(__half2*)&g_att[(size_t)(bb * SEQ + srow) * D_MODEL + d] =
                __floats2half2_rn(o[mt][nt][0] * il0, o[mt][nt][1] * il0);
            *(__half2*)&g_att[(size_t)(bb * SEQ + srow + 8) * D_MODEL + d] =
                __floats2half2_rn(o[mt][nt][2] * il1, o[mt][nt][3] * il1);
        }
    }
}

// ------------------------ launch --------------------------------------------
extern "C" void kernel_launch(void* const* d_in, const int* in_sizes, int n_in,
                              void* d_out, int out_size)
{
    const float* x    = (const float*)d_in[0];
    const float* Wqkv = (const float*)d_in[1];
    const float* bqkv = (const float*)d_in[2];
    const float* Wo   = (const float*)d_in[3];
    const float* bo   = (const float*)d_in[4];
    float* out = (float*)d_out;

    __half *p_xh, *p_att, *p_wqkvt, *p_wot;
    cudaGetSymbolAddress((void**)&p_xh, g_xh);
    cudaGetSymbolAddress((void**)&p_att, g_att);
    cudaGetSymbolAddress((void**)&p_wqkvt, g_wqkvt);
    cudaGetSymbolAddress((void**)&p_wot, g_wot);

    // fused prepass: x cvt + both weight transposes
    prepass_kernel<<<4096 + 768 + 256, 256>>>(x, Wqkv, Wo);

    // QKV projection + RoPE + split (fp16 q/k/vt, q pre-scaled)
    {
        cudaFuncSetAttribute(gemm_f16<1>,
                             cudaFuncAttributeMaxDynamicSharedMemorySize, GEMM_SMEM);
        dim3 grid(QKV_N / 128, M_ROWS / 128);
        gemm_f16<1><<<grid, 256, GEMM_SMEM>>>(p_xh, p_wqkvt, bqkv, nullptr, QKV_N);
    }
    // attention
    {
        cudaFuncSetAttribute(attention_f16,
                             cudaFuncAttributeMaxDynamicSharedMemorySize, AT_SMEM);
        dim3 grid(SEQ / 128, BATCH * NHEAD);
        attention_f16<<<grid, 128, AT_SMEM>>>();
    }
    // output projection (fp32 out)
    {
        cudaFuncSetAttribute(gemm_f16<0>,
                             cudaFuncAttributeMaxDynamicSharedMemorySize, GEMM_SMEM);
        dim3 grid(D_MODEL / 128, M_ROWS / 128);
        gemm_f16<0><<<grid, 256, GEMM_SMEM>>>(p_att, p_wot, bo, out, D_MODEL);
    }
}